// round 17
// baseline (speedup 1.0000x reference)
#include <cuda_runtime.h>
#include <math.h>

// R15 (59.9us, proven-resident 512 CTAs @ launch_bounds(256,4)) with ONE
// change: phase-1 tiles handed out by an atomic ticket counter instead of
// static assignment, eliminating the 4-vs-3-CTAs-per-SM straggler tail.
// Tile -> output slot mapping is fixed, so results are bit-identical
// regardless of which CTA runs which tile. Counter is reset by the barrier
// leader each launch -> graph-replay deterministic.

#define N 4096
#define SPLITS 512             // row splits (split-K)
#define ROWS_PER (N / SPLITS)  // 8 rows per split
#define PK_CTAS 512            // persistent CTAs (PROVEN co-resident in R15)
#define PK_THREADS 256
#define NUM_TILES 2048         // 4 col blocks x 512 splits

// Deterministic split-K scratch (8 MB).
__device__ float g_partial[SPLITS * N];

// Work-queue + grid-barrier state (self-resetting each launch).
__device__ unsigned int g_tile_counter = 0;
__device__ unsigned int g_bar_count = 0;
__device__ unsigned int g_bar_gen = 0;

// ---------------------------------------------------------------------------
// Kernel A: persistent matvec (work-stealing) + grid barrier + reduction.
// ---------------------------------------------------------------------------
__global__ void __launch_bounds__(PK_THREADS, 4) k_matvec_reduce(
    const float* __restrict__ input,
    const float* __restrict__ yin,
    const float* __restrict__ w,
    const float* __restrict__ alpha,
    const float* __restrict__ hebb,
    float* __restrict__ out_yout)
{
    const int tid = threadIdx.x;
    const int b   = blockIdx.x;
    const int stride4 = N / 4;

    __shared__ unsigned int s_tile;

    // ---------------- Phase 1: dynamic tile loop ----------------
    for (;;) {
        if (tid == 0)
            s_tile = atomicAdd(&g_tile_counter, 1);
        __syncthreads();
        const unsigned int tile = s_tile;
        __syncthreads();
        if (tile >= NUM_TILES) break;

        const int cb = (int)(tile & 3);            // column block 0..3
        const int sp = (int)(tile >> 2);           // split 0..511
        const int j  = cb * (PK_THREADS * 4) + tid * 4;
        const int r0 = sp * ROWS_PER;

        const float4* __restrict__ wp = reinterpret_cast<const float4*>(w     + (size_t)r0 * N + j);
        const float4* __restrict__ ap = reinterpret_cast<const float4*>(alpha + (size_t)r0 * N + j);
        const float4* __restrict__ hp = reinterpret_cast<const float4*>(hebb  + (size_t)r0 * N + j);

        float4 acc = make_float4(0.f, 0.f, 0.f, 0.f);

        #pragma unroll
        for (int i = 0; i < ROWS_PER; ++i) {
            const float  y  = __ldg(&yin[r0 + i]);
            const float4 w4 = __ldcs(wp + (size_t)i * stride4);
            const float4 a4 = __ldcs(ap + (size_t)i * stride4);
            const float4 h4 = __ldg (hp + (size_t)i * stride4);
            acc.x = fmaf(y, fmaf(a4.x, h4.x, w4.x), acc.x);
            acc.y = fmaf(y, fmaf(a4.y, h4.y, w4.y), acc.y);
            acc.z = fmaf(y, fmaf(a4.z, h4.z, w4.z), acc.z);
            acc.w = fmaf(y, fmaf(a4.w, h4.w, w4.w), acc.w);
        }

        *reinterpret_cast<float4*>(&g_partial[(size_t)sp * N + j]) = acc;
    }

    // ---------------- Grid barrier (last arriver resets queue) ----------------
    __syncthreads();
    if (tid == 0) {
        __threadfence();                                   // publish partials
        const unsigned int gen = atomicAdd(&g_bar_gen, 0);
        if (atomicAdd(&g_bar_count, 1) == (unsigned)(gridDim.x - 1)) {
            g_tile_counter = 0;                            // reset work queue
            g_bar_count = 0;                               // reset barrier
            __threadfence();
            atomicAdd(&g_bar_gen, 1);                      // release
        } else {
            while (atomicAdd(&g_bar_gen, 0) == gen) __nanosleep(32);
        }
        __threadfence();                                   // acquire
    }
    __syncthreads();

    // ---------------- Phase 2: reduction + tanh (CTAs 0..127) ----------------
    if (b < 128) {
        __shared__ float red[8][32];
        const int sg  = tid >> 5;                  // 0..7 split-group
        const int c   = tid & 31;                  // 0..31 col within CTA
        const int col = b * 32 + c;                // global column

        const float* __restrict__ gp = g_partial + (size_t)sg * (SPLITS / 8) * N + col;
        float s = 0.f;
        #pragma unroll 16
        for (int p = 0; p < SPLITS / 8; ++p)       // 64 partials, coalesced
            s += gp[(size_t)p * N];

        red[sg][c] = s;
        __syncthreads();

        if (sg == 0) {
            float tsum = red[0][c];
            #pragma unroll
            for (int g = 1; g < 8; ++g)
                tsum += red[g][c];
            out_yout[col] = tanhf(tsum + __ldg(&input[col]));
        }
    }
}

// ---------------------------------------------------------------------------
// Kernel B: flat hebb update (byte-identical to measured 18.6us version).
// ---------------------------------------------------------------------------
__global__ void __launch_bounds__(256) k_hebb_update(
    const float* __restrict__ hebb,
    const float* __restrict__ yin,
    const float* __restrict__ yout,   // = d_out
    const float* __restrict__ eta,
    float* __restrict__ out_hebb)     // = d_out + N
{
    const size_t t   = (size_t)blockIdx.x * blockDim.x + threadIdx.x;
    const size_t idx = t * 4;                 // element index in N*N
    const int i = (int)(idx >> 12);           // row (N = 2^12)
    const int j = (int)(idx & (N - 1));       // col

    const float e   = eta[0];
    const float ome = 1.f - e;
    const float yie = yin[i] * e;             // warp-uniform broadcast

    const float4 h  = __ldg(reinterpret_cast<const float4*>(hebb + idx));
    const float4 yo = __ldg(reinterpret_cast<const float4*>(yout + j));

    float4 r;
    r.x = fmaf(ome, h.x, yie * yo.x);
    r.y = fmaf(ome, h.y, yie * yo.y);
    r.z = fmaf(ome, h.z, yie * yo.z);
    r.w = fmaf(ome, h.w, yie * yo.w);

    __stcs(reinterpret_cast<float4*>(out_hebb + idx), r);
}

extern "C" void kernel_launch(void* const* d_in, const int* in_sizes, int n_in,
                              void* d_out, int out_size)
{
    const float* input = (const float*)d_in[0];
    const float* yin   = (const float*)d_in[1];
    const float* hebb  = (const float*)d_in[2];
    const float* w     = (const float*)d_in[3];
    const float* alpha = (const float*)d_in[4];
    const float* eta   = (const float*)d_in[5];

    float* out      = (float*)d_out;
    float* out_yout = out;
    float* out_hebb = out + N;

    k_matvec_reduce<<<PK_CTAS, PK_THREADS>>>(input, yin, w, alpha, hebb, out_yout);

    const int hb_blocks = (N * N) / (4 * 256);   // 16384
    k_hebb_update<<<hb_blocks, 256>>>(hebb, yin, out_yout, eta, out_hebb);
}